// round 1
// baseline (speedup 1.0000x reference)
#include <cuda_runtime.h>
#include <math.h>

// Problem constants (fixed by reference: B=4, S=4096, D=2048, E=64, K=2)
#define M_TOKENS 16384
#define D_DIM    2048
#define E_EXP    64
#define TM       64     // tokens per CTA
#define TK       32     // k-tile
#define NCTA     (M_TOKENS / TM)   // 256

// Per-CTA partials: [cta][0:64)=counts, [cta][64:128)=sum of probs per expert.
// Fully overwritten every launch -> deterministic, no zeroing needed.
__device__ float g_partials[NCTA * 128];

__global__ __launch_bounds__(256, 2)
void router_gemm_kernel(const float* __restrict__ x,
                        const float* __restrict__ W,
                        float* __restrict__ out)
{
    __shared__ float xs[TK][TM + 4];        // [k][token]
    __shared__ float ws[TK][E_EXP + 4];     // [k][expert]
    __shared__ float probs[TM][E_EXP + 4];  // logits -> probs
    __shared__ int   tops[TM][2];

    const int tid  = threadIdx.x;
    const int cta  = blockIdx.x;
    const long tbase = (long)cta * TM;

    const int tc = tid & 15;   // expert group: experts [tc*4, tc*4+4)
    const int tr = tid >> 4;   // token group:  tokens  [tr*4, tr*4+4)

    float acc[4][4];
    #pragma unroll
    for (int i = 0; i < 4; i++)
        #pragma unroll
        for (int j = 0; j < 4; j++)
            acc[i][j] = 0.0f;

    for (int k0 = 0; k0 < D_DIM; k0 += TK) {
        // Load x tile (64 tokens x 32 k) and W tile (64 experts x 32 k),
        // transposed into [k][.] layout. 2 float4 per thread per tensor.
        #pragma unroll
        for (int p = 0; p < 2; p++) {
            int idx = tid + p * 256;
            int row = idx >> 3;          // 0..63
            int c4  = (idx & 7) << 2;    // 0,4,...,28
            float4 xv = *reinterpret_cast<const float4*>(
                x + (tbase + row) * (long)D_DIM + k0 + c4);
            xs[c4 + 0][row] = xv.x;
            xs[c4 + 1][row] = xv.y;
            xs[c4 + 2][row] = xv.z;
            xs[c4 + 3][row] = xv.w;
            float4 wv = *reinterpret_cast<const float4*>(
                W + (long)row * D_DIM + k0 + c4);
            ws[c4 + 0][row] = wv.x;
            ws[c4 + 1][row] = wv.y;
            ws[c4 + 2][row] = wv.z;
            ws[c4 + 3][row] = wv.w;
        }
        __syncthreads();

        #pragma unroll
        for (int k = 0; k < TK; k++) {
            float4 xv = *reinterpret_cast<const float4*>(&xs[k][tr << 2]);
            float4 wv = *reinterpret_cast<const float4*>(&ws[k][tc << 2]);
            float xr[4] = {xv.x, xv.y, xv.z, xv.w};
            float wr[4] = {wv.x, wv.y, wv.z, wv.w};
            #pragma unroll
            for (int i = 0; i < 4; i++)
                #pragma unroll
                for (int j = 0; j < 4; j++)
                    acc[i][j] = fmaf(xr[i], wr[j], acc[i][j]);
        }
        __syncthreads();
    }

    // Dump logits to shared.
    #pragma unroll
    for (int i = 0; i < 4; i++)
        #pragma unroll
        for (int j = 0; j < 4; j++)
            probs[(tr << 2) + i][(tc << 2) + j] = acc[i][j];
    __syncthreads();

    // Per-token softmax + top-2 + gate + output writes. One thread per token.
    if (tid < TM) {
        const int t = tid;
        float mx = -1e30f;
        #pragma unroll
        for (int e = 0; e < E_EXP; e++) mx = fmaxf(mx, probs[t][e]);
        float sum = 0.0f;
        #pragma unroll
        for (int e = 0; e < E_EXP; e++) {
            float p = expf(probs[t][e] - mx);
            probs[t][e] = p;
            sum += p;
        }
        const float inv = 1.0f / sum;
        float b1 = -1.0f, b2 = -1.0f;
        int i1 = 0, i2 = 0;
        #pragma unroll
        for (int e = 0; e < E_EXP; e++) {
            float p = probs[t][e] * inv;
            probs[t][e] = p;
            if (p > b1) { b2 = b1; i2 = i1; b1 = p; i1 = e; }
            else if (p > b2) { b2 = p; i2 = e; }
        }
        const float denom = b1 + b2 + 1e-9f;
        const long gt = tbase + t;
        out[gt * 2 + 0] = (float)i1;                        // top_k_indices
        out[gt * 2 + 1] = (float)i2;
        out[(long)M_TOKENS * 2 + gt * 2 + 0] = b1 / denom;  // top_k_gates
        out[(long)M_TOKENS * 2 + gt * 2 + 1] = b2 / denom;
        tops[t][0] = i1;
        tops[t][1] = i2;
    }
    __syncthreads();

    // Deterministic per-CTA reduction: counts and sum-of-probs per expert.
    if (tid < E_EXP) {
        const int e = tid;
        float cnt = 0.0f, sp = 0.0f;
        #pragma unroll 4
        for (int t = 0; t < TM; t++) {
            cnt += (float)((tops[t][0] == e) + (tops[t][1] == e));
            sp  += probs[t][e];
        }
        g_partials[cta * 128 + e]      = cnt;
        g_partials[cta * 128 + 64 + e] = sp;
    }
}

__global__ void aux_kernel(float* __restrict__ out)
{
    __shared__ float sdata[64];
    const int e = threadIdx.x;   // 64 threads
    float C = 0.0f, P = 0.0f;
    for (int c = 0; c < NCTA; c++) {
        C += g_partials[c * 128 + e];
        P += g_partials[c * 128 + 64 + e];
    }
    sdata[e] = C * P;
    __syncthreads();
    #pragma unroll
    for (int s = 32; s > 0; s >>= 1) {
        if (e < s) sdata[e] += sdata[e + s];
        __syncthreads();
    }
    if (e == 0) {
        // aux = 0.01 * E * sum_e (counts/total_slots) * (sumprobs/M)
        out[(long)M_TOKENS * 4] =
            0.01f * 64.0f * sdata[0] / (32768.0f * 16384.0f);
    }
}

extern "C" void kernel_launch(void* const* d_in, const int* in_sizes, int n_in,
                              void* d_out, int out_size)
{
    const float* x = (const float*)d_in[0];   // [4,4096,2048] f32
    const float* W = (const float*)d_in[1];   // [64,2048] f32
    float* out = (float*)d_out;               // [32768 idx | 32768 gates | 1 aux]

    router_gemm_kernel<<<NCTA, 256>>>(x, W, out);
    aux_kernel<<<1, 64>>>(out);
}

// round 5
// speedup vs baseline: 1.0185x; 1.0185x over previous
#include <cuda_runtime.h>
#include <math.h>
#include <stdint.h>

// Problem: B=4, S=4096, D=2048, E=64, K=2
#define M_TOKENS 16384
#define D_DIM    2048
#define E_EXP    64
#define TM       128                  // tokens per CTA
#define TKC      16                   // K per chunk
#define NCHUNK   (D_DIM / TKC)        // 128
#define NCTA     (M_TOKENS / TM)      // 128
#define NTHREADS 256
#define DRAIN    8                    // drain acc->double every 8 chunks

// smem stage: x tile [128 rows x 20 floats pad], W tile [64 x 20]
#define XS_FLOATS (128 * 20)          // 2560
#define WS_FLOATS (64 * 20)           // 1280
#define STAGE_FLOATS (XS_FLOATS + WS_FLOATS)   // 3840 (15360 B)
#define NSTAGE 3

// per-CTA partials: [cta][0:64)=counts, [cta][64:128)=prob sums
__device__ float g_partials[NCTA * 128];

#define CP16(smem_a, gptr) \
    asm volatile("cp.async.cg.shared.global [%0], [%1], 16;" \
                 :: "r"(smem_a), "l"(gptr) : "memory")
#define CP_COMMIT() asm volatile("cp.async.commit_group;" ::: "memory")
#define CP_WAIT1()  asm volatile("cp.async.wait_group 1;" ::: "memory")

static __device__ __forceinline__ uint32_t smem_u32(const void* p) {
    uint32_t r;
    asm("{ .reg .u64 t; cvta.to.shared.u64 t, %1; cvt.u32.u64 %0, t; }"
        : "=r"(r) : "l"(p));
    return r;
}

static __device__ __forceinline__ void mma_tf32(float* d,
        uint32_t a0, uint32_t a1, uint32_t a2, uint32_t a3,
        uint32_t b0, uint32_t b1) {
    asm volatile(
        "mma.sync.aligned.m16n8k8.row.col.f32.tf32.tf32.f32 "
        "{%0,%1,%2,%3},{%4,%5,%6,%7},{%8,%9},{%0,%1,%2,%3};"
        : "+f"(d[0]), "+f"(d[1]), "+f"(d[2]), "+f"(d[3])
        : "r"(a0), "r"(a1), "r"(a2), "r"(a3), "r"(b0), "r"(b1));
}

// hi = v with mantissa truncated to 10 bits (exact tf32), lo = v - hi (exact fp32).
// 3-pass emulation (hh + hl + lh) drops only lo*lo terms (~2^-22 rel).
static __device__ __forceinline__ void split1(float v, uint32_t& hi, uint32_t& lo) {
    uint32_t uv = __float_as_uint(v);
    hi = uv & 0xFFFFE000u;
    lo = __float_as_uint(v - __uint_as_float(hi));
}

__global__ __launch_bounds__(NTHREADS, 1)
void router_mma(const float* __restrict__ x, const float* __restrict__ W,
                float* __restrict__ out)
{
    __shared__ __align__(16) float smem[NSTAGE][STAGE_FLOATS];
    __shared__ int tops[TM][2];

    const int tid  = threadIdx.x;
    const int wid  = tid >> 5;     // warp owns token rows [16*wid, 16*wid+16)
    const int lane = tid & 31;
    const int qr   = lane >> 2;    // groupID 0..7
    const int qc   = lane & 3;     // threadID-in-group 0..3
    const int cta  = blockIdx.x;
    const size_t tbase = (size_t)cta * TM;

    const uint32_t sbase = smem_u32(&smem[0][0]);

    auto load_chunk = [&](int c, int s) {
        const int k0 = c * TKC;
        const uint32_t sx = sbase + (uint32_t)s * (STAGE_FLOATS * 4);
#pragma unroll
        for (int p = 0; p < 2; p++) {                 // x: 512 segs of 16B
            int seg = tid + p * NTHREADS;
            int row = seg >> 2, c4 = (seg & 3) << 2;
            const float* g = x + (tbase + row) * (size_t)D_DIM + k0 + c4;
            CP16(sx + row * 80 + c4 * 4, g);
        }
        {                                             // W: 256 segs
            int row = tid >> 2, c4 = (tid & 3) << 2;
            const float* g = W + (size_t)row * D_DIM + k0 + c4;
            CP16(sx + XS_FLOATS * 4 + row * 80 + c4 * 4, g);
        }
    };

    float  acc[8][4];
    double dsum[8][4];
#pragma unroll
    for (int n = 0; n < 8; n++)
#pragma unroll
        for (int j = 0; j < 4; j++) { acc[n][j] = 0.0f; dsum[n][j] = 0.0; }

    load_chunk(0, 0); CP_COMMIT();
    load_chunk(1, 1); CP_COMMIT();

    const int arow0 = (wid * 16 + qr) * 20;
    const int arow1 = arow0 + 8 * 20;

    for (int c = 0; c < NCHUNK; c++) {
        CP_WAIT1();
        __syncthreads();
        if (c + 2 < NCHUNK) load_chunk(c + 2, (c + 2) % NSTAGE);
        CP_COMMIT();

        const float* xs = &smem[c % NSTAGE][0];
        const float* ws = xs + XS_FLOATS;
#pragma unroll
        for (int kk = 0; kk < TKC; kk += 8) {
            const int kc = kk + qc;
            uint32_t ah0, al0, ah1, al1, ah2, al2, ah3, al3;
            split1(xs[arow0 + kc],     ah0, al0);
            split1(xs[arow1 + kc],     ah1, al1);
            split1(xs[arow0 + kc + 4], ah2, al2);
            split1(xs[arow1 + kc + 4], ah3, al3);
#pragma unroll
            for (int n = 0; n < 8; n++) {
                uint32_t bh0, bl0, bh1, bl1;
                split1(ws[(n * 8 + qr) * 20 + kc],     bh0, bl0);
                split1(ws[(n * 8 + qr) * 20 + kc + 4], bh1, bl1);
                mma_tf32(acc[n], ah0, ah1, ah2, ah3, bh0, bh1);
                mma_tf32(acc[n], ah0, ah1, ah2, ah3, bl0, bl1);
                mma_tf32(acc[n], al0, al1, al2, al3, bh0, bh1);
            }
        }

        // Drain fp32 MMA accumulators into fp64 sums every DRAIN chunks.
        // Caps the fp32 rounding chain at 48 adds (noise ~6e-8/group).
        if ((c & (DRAIN - 1)) == (DRAIN - 1)) {
#pragma unroll
            for (int n = 0; n < 8; n++)
#pragma unroll
                for (int j = 0; j < 4; j++) {
                    dsum[n][j] += (double)acc[n][j];
                    acc[n][j] = 0.0f;
                }
        }
    }
    __syncthreads();

    // ---- epilogue: logits to smem overlay [128][66] ----
    float* probs = &smem[0][0];
    const int tr0 = wid * 16 + qr, tr1 = tr0 + 8;
#pragma unroll
    for (int n = 0; n < 8; n++) {
        const int cb = n * 8 + qc * 2;
        *reinterpret_cast<float2*>(&probs[tr0 * 66 + cb]) =
            make_float2((float)dsum[n][0], (float)dsum[n][1]);
        *reinterpret_cast<float2*>(&probs[tr1 * 66 + cb]) =
            make_float2((float)dsum[n][2], (float)dsum[n][3]);
    }
    __syncthreads();

    // one thread per token: softmax + top-2 + gates + outputs
    if (tid < TM) {
        const int t = tid;
        float f[64];
#pragma unroll
        for (int e = 0; e < E_EXP; e++) f[e] = probs[t * 66 + e];
        float mx = f[0];
#pragma unroll
        for (int e = 1; e < E_EXP; e++) mx = fmaxf(mx, f[e]);
        float S = 0.0f, b1 = -1.0f, b2 = -1.0f;
        int i1 = 0, i2 = 0;
#pragma unroll
        for (int e = 0; e < E_EXP; e++) {
            float v = expf(f[e] - mx);
            f[e] = v;
            S += v;
            if (v > b1) { b2 = b1; i2 = i1; b1 = v; i1 = e; }
            else if (v > b2) { b2 = v; i2 = e; }
        }
        const float invS = 1.0f / S;
#pragma unroll
        for (int e = 0; e < E_EXP; e++) probs[t * 66 + e] = f[e] * invS;
        tops[t][0] = i1;
        tops[t][1] = i2;

        const float p1 = b1 * invS, p2 = b2 * invS;
        const float denom = p1 + p2 + 1e-9f;
        const size_t gt = tbase + t;
        out[gt * 2 + 0] = (float)i1;
        out[gt * 2 + 1] = (float)i2;
        out[(size_t)M_TOKENS * 2 + gt * 2 + 0] = p1 / denom;
        out[(size_t)M_TOKENS * 2 + gt * 2 + 1] = p2 / denom;
    }
    __syncthreads();

    // deterministic per-CTA partials (counts, prob sums)
    if (tid < E_EXP) {
        const int e = tid;
        float cnt = 0.0f, sp = 0.0f;
#pragma unroll 4
        for (int t = 0; t < TM; t++) {
            sp  += probs[t * 66 + e];
            cnt += (float)((tops[t][0] == e) + (tops[t][1] == e));
        }
        g_partials[cta * 128 + e]      = cnt;
        g_partials[cta * 128 + 64 + e] = sp;
    }
}

__global__ void aux_kernel2(float* __restrict__ out)
{
    __shared__ float sC[16][64];
    __shared__ float sP[16][64];
    __shared__ float red[64];
    const int t = threadIdx.x;          // 1024 threads
    const int c = t >> 6, e = t & 63;
    float C = 0.0f, P = 0.0f;
#pragma unroll
    for (int j = 0; j < 8; j++) {
        const int b = c + 16 * j;
        C += g_partials[b * 128 + e];
        P += g_partials[b * 128 + 64 + e];
    }
    sC[c][e] = C; sP[c][e] = P;
    __syncthreads();
    if (t < 64) {
        float Ct = 0.0f, Pt = 0.0f;
#pragma unroll
        for (int j = 0; j < 16; j++) { Ct += sC[j][t]; Pt += sP[j][t]; }
        red[t] = Ct * Pt;
    }
    __syncthreads();
#pragma unroll
    for (int s = 32; s > 0; s >>= 1) {
        if (t < s) red[t] += red[t + s];
        __syncthreads();
    }
    if (t == 0)
        out[(size_t)M_TOKENS * 4] =
            0.01f * 64.0f * red[0] / (32768.0f * 16384.0f);
}

extern "C" void kernel_launch(void* const* d_in, const int* in_sizes, int n_in,
                              void* d_out, int out_size)
{
    const float* x = (const float*)d_in[0];   // [4,4096,2048] f32
    const float* W = (const float*)d_in[1];   // [64,2048] f32
    float* out = (float*)d_out;               // [32768 idx | 32768 gates | 1 aux]

    router_mma<<<NCTA, NTHREADS>>>(x, W, out);
    aux_kernel2<<<1, 1024>>>(out);
}

// round 6
// speedup vs baseline: 1.3976x; 1.3722x over previous
#include <cuda_runtime.h>
#include <math.h>
#include <stdint.h>

// Problem: B=4, S=4096, D=2048, E=64, K=2
#define M_TOKENS 16384
#define D_DIM    2048
#define E_EXP    64
#define TM       128                   // tokens per CTA
#define TKC      32                    // K per chunk
#define NCHUNK   (D_DIM / TKC)         // 64
#define NCTA     (M_TOKENS / TM)       // 128
#define NTHREADS 256

#define XS_STRIDE 36                   // floats per token row (pad: conflict-free)
#define XS_BYTES  (TM * XS_STRIDE * 4) // 18432
#define WS_BYTES  (TKC * 16 * 16)      // 8192  (32 k-rows x 16 granules x 16B)
#define STAGE_BYTES (XS_BYTES + WS_BYTES)  // 26624
#define DYN_BYTES (2 * STAGE_BYTES)        // 53248

// per-CTA partials: [cta][0:64)=counts, [cta][64:128)=prob sums
__device__ float g_partials[NCTA * 128];
// W transposed to [k][e], 16B granules swizzled with q^(q>>3) per k-row.
__device__ __align__(16) float g_wt[D_DIM * E_EXP];

#define CP16(smem_a, gptr) \
    asm volatile("cp.async.cg.shared.global [%0], [%1], 16;" \
                 :: "r"(smem_a), "l"(gptr) : "memory")
#define CP_COMMIT() asm volatile("cp.async.commit_group;" ::: "memory")
#define CP_WAIT1()  asm volatile("cp.async.wait_group 1;" ::: "memory")

static __device__ __forceinline__ uint32_t smem_u32(const void* p) {
    uint32_t r;
    asm("{ .reg .u64 t; cvta.to.shared.u64 t, %1; cvt.u32.u64 %0, t; }"
        : "=r"(r) : "l"(p));
    return r;
}

// packed fp32 FMA: acc {lo,hi} += a {lo,hi} * b {lo,hi}
static __device__ __forceinline__ void fma2(uint64_t& acc, uint64_t a, uint64_t b) {
    asm("fma.rn.f32x2 %0, %1, %2, %0;" : "+l"(acc) : "l"(a), "l"(b));
}
static __device__ __forceinline__ uint64_t dup2(float v) {
    uint64_t r;
    asm("mov.b64 %0, {%1, %1};" : "=l"(r) : "f"(v));
    return r;
}
static __device__ __forceinline__ void lds_v2u64(uint64_t& a, uint64_t& b, uint32_t addr) {
    asm volatile("ld.shared.v2.u64 {%0, %1}, [%2];" : "=l"(a), "=l"(b) : "r"(addr));
}

// ---- pre-kernel: build swizzled W-transpose image ----
// logical (k, q): granule q (16B = experts 4q..4q+3 at column k)
// stored at g_wt granule [k*16 + (q ^ (q>>3))]
__global__ void wt_kernel(const float* __restrict__ W)
{
    int g = blockIdx.x * blockDim.x + threadIdx.x;   // 0..32767
    int k = g >> 4;
    int q = g & 15;
    float4 v;
    v.x = W[(size_t)(4 * q + 0) * D_DIM + k];
    v.y = W[(size_t)(4 * q + 1) * D_DIM + k];
    v.z = W[(size_t)(4 * q + 2) * D_DIM + k];
    v.w = W[(size_t)(4 * q + 3) * D_DIM + k];
    int sw = q ^ (q >> 3);
    *reinterpret_cast<float4*>(&g_wt[(size_t)(k * 16 + sw) * 4]) = v;
}

__global__ __launch_bounds__(NTHREADS, 1)
void router_f32x2(const float* __restrict__ x, float* __restrict__ out)
{
    extern __shared__ __align__(16) char dsm[];
    __shared__ int tops[TM][2];

    const int tid = threadIdx.x;
    const int row = tid >> 3;          // 0..31 -> tokens {row, row+32, row+64, row+96}
    const int col = tid & 7;           // expert-pairs col*4..col*4+3 (experts col*8..+7)
    const int cta = blockIdx.x;
    const size_t tbase = (size_t)cta * TM;

    const uint32_t sb0 = smem_u32(dsm);

    // ---- async tile loader: chunk c -> stage s ----
    auto load_chunk = [&](int c, int s) {
        const int k0 = c * TKC;
        const uint32_t bs = sb0 + (uint32_t)s * STAGE_BYTES;
#pragma unroll
        for (int p = 0; p < 4; p++) {              // x: 1024 segs of 16B
            int seg = tid + p * NTHREADS;
            int t = seg >> 3, sk = seg & 7;
            const float* g = x + (tbase + t) * (size_t)D_DIM + k0 + sk * 4;
            CP16(bs + (uint32_t)(t * XS_STRIDE + sk * 4) * 4, g);
        }
#pragma unroll
        for (int p = 0; p < 2; p++) {              // W image: 512 granules, contiguous
            int seg = tid + p * NTHREADS;
            const float* g = g_wt + (size_t)(c * 512 + seg) * 4;
            CP16(bs + XS_BYTES + (uint32_t)seg * 16, g);
        }
    };

    uint64_t acc[4][4];                 // [token j][expert-pair p] packed {e, e+1}
#pragma unroll
    for (int j = 0; j < 4; j++)
#pragma unroll
        for (int p = 0; p < 4; p++) acc[j][p] = 0ull;

    load_chunk(0, 0); CP_COMMIT();
    load_chunk(1, 1); CP_COMMIT();

    const int q1 = col * 2, q2 = col * 2 + 1;
    const uint32_t wso1 = (uint32_t)((q1 ^ (q1 >> 3)) * 16);
    const uint32_t wso2 = (uint32_t)((q2 ^ (q2 >> 3)) * 16);

    for (int c = 0; c < NCHUNK; c++) {
        CP_WAIT1();                     // oldest group (chunk c) resident
        __syncthreads();

        const int s = c & 1;
        const float* xs = reinterpret_cast<const float*>(dsm + s * STAGE_BYTES);
        const uint32_t wsu = sb0 + (uint32_t)s * STAGE_BYTES + XS_BYTES;

#pragma unroll 2
        for (int kk = 0; kk < TKC; kk += 4) {
            float4 xv[4];
#pragma unroll
            for (int j = 0; j < 4; j++)
                xv[j] = *reinterpret_cast<const float4*>(
                    &xs[(row + 32 * j) * XS_STRIDE + kk]);
#pragma unroll
            for (int dk = 0; dk < 4; dk++) {
                uint64_t b0, b1, b2, b3;
                const uint32_t kb = wsu + (uint32_t)(kk + dk) * 256;
                lds_v2u64(b0, b1, kb + wso1);
                lds_v2u64(b2, b3, kb + wso2);
#pragma unroll
                for (int j = 0; j < 4; j++) {
                    float xf = (dk == 0) ? xv[j].x : (dk == 1) ? xv[j].y
                             : (dk == 2) ? xv[j].z : xv[j].w;
                    uint64_t xx = dup2(xf);
                    fma2(acc[j][0], xx, b0);
                    fma2(acc[j][1], xx, b1);
                    fma2(acc[j][2], xx, b2);
                    fma2(acc[j][3], xx, b3);
                }
            }
        }
        __syncthreads();                // stage s free for reload
        if (c + 2 < NCHUNK) load_chunk(c + 2, s);
        CP_COMMIT();                    // uniform group count (may be empty)
    }

    // ---- epilogue: logits to smem overlay [128][66] (both stages dead) ----
    float* probs = reinterpret_cast<float*>(dsm);
#pragma unroll
    for (int j = 0; j < 4; j++) {
        const int t = row + 32 * j;
#pragma unroll
        for (int p = 0; p < 4; p++) {
            const uint64_t a = acc[j][p];
            float lo = __uint_as_float((uint32_t)a);
            float hi = __uint_as_float((uint32_t)(a >> 32));
            *reinterpret_cast<float2*>(&probs[t * 66 + col * 8 + p * 2]) =
                make_float2(lo, hi);
        }
    }
    __syncthreads();

    // one thread per token: softmax + top-2 + gates + outputs
    if (tid < TM) {
        const int t = tid;
        float f[64];
#pragma unroll
        for (int e = 0; e < E_EXP; e++) f[e] = probs[t * 66 + e];
        float mx = f[0];
#pragma unroll
        for (int e = 1; e < E_EXP; e++) mx = fmaxf(mx, f[e]);
        float S = 0.0f, b1 = -1.0f, b2 = -1.0f;
        int i1 = 0, i2 = 0;
#pragma unroll
        for (int e = 0; e < E_EXP; e++) {
            float v = expf(f[e] - mx);
            f[e] = v;
            S += v;
            if (v > b1) { b2 = b1; i2 = i1; b1 = v; i1 = e; }
            else if (v > b2) { b2 = v; i2 = e; }
        }
        const float invS = 1.0f / S;
#pragma unroll
        for (int e = 0; e < E_EXP; e++) probs[t * 66 + e] = f[e] * invS;
        tops[t][0] = i1;
        tops[t][1] = i2;

        const float p1 = b1 * invS, p2 = b2 * invS;
        const float denom = p1 + p2 + 1e-9f;
        const size_t gt = tbase + t;
        out[gt * 2 + 0] = (float)i1;
        out[gt * 2 + 1] = (float)i2;
        out[(size_t)M_TOKENS * 2 + gt * 2 + 0] = p1 / denom;
        out[(size_t)M_TOKENS * 2 + gt * 2 + 1] = p2 / denom;
    }
    __syncthreads();

    // deterministic per-CTA partials (counts, prob sums)
    if (tid < E_EXP) {
        const int e = tid;
        float cnt = 0.0f, sp = 0.0f;
#pragma unroll 4
        for (int t = 0; t < TM; t++) {
            sp  += probs[t * 66 + e];
            cnt += (float)((tops[t][0] == e) + (tops[t][1] == e));
        }
        g_partials[cta * 128 + e]      = cnt;
        g_partials[cta * 128 + 64 + e] = sp;
    }
}

__global__ void aux_kernel2(float* __restrict__ out)
{
    __shared__ float sC[16][64];
    __shared__ float sP[16][64];
    __shared__ float red[64];
    const int t = threadIdx.x;          // 1024 threads
    const int c = t >> 6, e = t & 63;
    float C = 0.0f, P = 0.0f;
#pragma unroll
    for (int j = 0; j < 8; j++) {
        const int b = c + 16 * j;
        C += g_partials[b * 128 + e];
        P += g_partials[b * 128 + 64 + e];
    }
    sC[c][e] = C; sP[c][e] = P;
    __syncthreads();
    if (t < 64) {
        float Ct = 0.0f, Pt = 0.0f;
#pragma unroll
        for (int j = 0; j < 16; j++) { Ct += sC[j][t]; Pt += sP[j][t]; }
        red[t] = Ct * Pt;
    }
    __syncthreads();
#pragma unroll
    for (int s = 32; s > 0; s >>= 1) {
        if (t < s) red[t] += red[t + s];
        __syncthreads();
    }
    if (t == 0)
        out[(size_t)M_TOKENS * 4] =
            0.01f * 64.0f * red[0] / (32768.0f * 16384.0f);
}

extern "C" void kernel_launch(void* const* d_in, const int* in_sizes, int n_in,
                              void* d_out, int out_size)
{
    const float* x = (const float*)d_in[0];   // [4,4096,2048] f32
    const float* W = (const float*)d_in[1];   // [64,2048] f32
    float* out = (float*)d_out;               // [32768 idx | 32768 gates | 1 aux]

    cudaFuncSetAttribute(router_f32x2,
                         cudaFuncAttributeMaxDynamicSharedMemorySize, DYN_BYTES);

    wt_kernel<<<128, 256>>>(W);
    router_f32x2<<<NCTA, NTHREADS, DYN_BYTES>>>(x, out);
    aux_kernel2<<<1, 1024>>>(out);
}